// round 2
// baseline (speedup 1.0000x reference)
#include <cuda_runtime.h>
#include <cstdint>

#define NV 50000
#define NE_MAX 400000
#define H 128

// Scratch (no cudaMalloc allowed): aggregated neighbor features + degree.
__device__ float g_agg[(size_t)NV * H];   // 25.6 MB
__device__ float g_deg[NV];

// ---------------------------------------------------------------------------
// Zero scratch each launch (graph replays must be deterministic).
// ---------------------------------------------------------------------------
__global__ void k_zero() {
    size_t i = (size_t)blockIdx.x * blockDim.x + threadIdx.x;
    size_t stride = (size_t)gridDim.x * blockDim.x;
    for (size_t t = i; t < (size_t)NV * H; t += stride) g_agg[t] = 0.0f;
    for (size_t t = i; t < (size_t)NV;     t += stride) g_deg[t] = 0.0f;
}

// ---------------------------------------------------------------------------
// Scatter phase: one warp per directed edge. Each lane moves one float4
// (128 floats / 32 lanes). Vector reduction (red.global.add.v4.f32) keeps the
// L2 atomic-op count at 1 per 16B instead of 1 per 4B.
// ---------------------------------------------------------------------------
__global__ void k_scatter(const float* __restrict__ x,
                          const int* __restrict__ ei, int nE) {
    int gw   = (int)(((unsigned)blockIdx.x * blockDim.x + threadIdx.x) >> 5);
    int lane = threadIdx.x & 31;
    if (gw >= 2 * nE) return;

    int s, d;
    if (gw < nE) { s = ei[gw];      d = ei[nE + gw]; }
    else         { int e = gw - nE; d = ei[e]; s = ei[nE + e]; }

    const float4* xs = reinterpret_cast<const float4*>(x + (size_t)s * H);
    float4 v = xs[lane];

    float4* ag = reinterpret_cast<float4*>(g_agg + (size_t)d * H) + lane;
    asm volatile("red.global.add.v4.f32 [%0], {%1, %2, %3, %4};"
                 :: "l"(ag), "f"(v.x), "f"(v.y), "f"(v.z), "f"(v.w)
                 : "memory");

    if (lane == 0) atomicAdd(&g_deg[d], 1.0f);
}

// ---------------------------------------------------------------------------
// GEMM phase: out[M=NV, N=128] = A[M, K=256] @ B[K=256, N=128]
//   A[:, 0:128)   = agg
//   A[:, 128:256) = deg(row) * x
//   B[k][j]       = W[j][k]      (W is [128, 256] row-major)
// Classic 128x128x8 register-tiled SGEMM, 256 threads, 8x8 microtile.
// ---------------------------------------------------------------------------
#define BM 128
#define BN 128
#define BK 8
#define TM 8
#define TN 8

__global__ __launch_bounds__(256)
void k_gemm(const float* __restrict__ x, const float* __restrict__ W,
            float* __restrict__ out) {
    __shared__ __align__(16) float As[BK][BM];
    __shared__ __align__(16) float Bs[BK][BN];

    int tid = threadIdx.x;
    int tx = tid & 15;      // 16 column groups
    int ty = tid >> 4;      // 16 row groups
    int row0 = blockIdx.x * BM;

    float acc[TM][TN];
#pragma unroll
    for (int i = 0; i < TM; i++)
#pragma unroll
        for (int j = 0; j < TN; j++) acc[i][j] = 0.0f;

    // A-tile load map: 128 rows x 8 k, float4 per thread
    int arow = tid >> 1;
    int akq  = (tid & 1) * 4;
    // B-tile load map: 8 k x 128 cols; thread reads 4 consecutive k of one W row
    int bj  = tid & 127;
    int bkq = (tid >> 7) * 4;

    for (int k0 = 0; k0 < 2 * H; k0 += BK) {
        // ---- load A tile (transposed into As[k][row]) ----
        {
            int grow = row0 + arow;
            float4 av = make_float4(0.f, 0.f, 0.f, 0.f);
            if (grow < NV) {
                if (k0 < H) {
                    av = *reinterpret_cast<const float4*>(
                        g_agg + (size_t)grow * H + k0 + akq);
                } else {
                    av = *reinterpret_cast<const float4*>(
                        x + (size_t)grow * H + (k0 - H) + akq);
                    float dg = g_deg[grow];
                    av.x *= dg; av.y *= dg; av.z *= dg; av.w *= dg;
                }
            }
            As[akq + 0][arow] = av.x;
            As[akq + 1][arow] = av.y;
            As[akq + 2][arow] = av.z;
            As[akq + 3][arow] = av.w;
        }
        // ---- load B tile: Bs[kk][j] = W[j][k0+kk] ----
        {
            float4 wv = *reinterpret_cast<const float4*>(
                W + (size_t)bj * (2 * H) + k0 + bkq);
            Bs[bkq + 0][bj] = wv.x;
            Bs[bkq + 1][bj] = wv.y;
            Bs[bkq + 2][bj] = wv.z;
            Bs[bkq + 3][bj] = wv.w;
        }
        __syncthreads();

#pragma unroll
        for (int kk = 0; kk < BK; kk++) {
            float a[TM], b[TN];
#pragma unroll
            for (int i = 0; i < TM; i++) a[i] = As[kk][ty * TM + i];
#pragma unroll
            for (int j = 0; j < TN; j++) b[j] = Bs[kk][tx * TN + j];
#pragma unroll
            for (int i = 0; i < TM; i++)
#pragma unroll
                for (int j = 0; j < TN; j++)
                    acc[i][j] += a[i] * b[j];
        }
        __syncthreads();
    }

    // ---- epilogue ----
#pragma unroll
    for (int i = 0; i < TM; i++) {
        int grow = row0 + ty * TM + i;
        if (grow < NV) {
            float4* o = reinterpret_cast<float4*>(
                out + (size_t)grow * H + tx * TN);
            o[0] = make_float4(acc[i][0], acc[i][1], acc[i][2], acc[i][3]);
            o[1] = make_float4(acc[i][4], acc[i][5], acc[i][6], acc[i][7]);
        }
    }
}

// ---------------------------------------------------------------------------
extern "C" void kernel_launch(void* const* d_in, const int* in_sizes, int n_in,
                              void* d_out, int out_size) {
    const float* x  = (const float*)d_in[0];   // [NV, 128] f32
    const float* W  = (const float*)d_in[1];   // [128, 256] f32
    const int*   ei = (const int*)d_in[2];     // [2, E] i32
    float* out = (float*)d_out;                // [NV, 128] f32

    int nE = in_sizes[2] / 2;

    k_zero<<<1024, 256>>>();

    int nwarps  = 2 * nE;                      // one warp per directed edge
    int nblocks = (nwarps * 32 + 255) / 256;
    k_scatter<<<nblocks, 256>>>(x, ei, nE);

    k_gemm<<<(NV + BM - 1) / BM, 256>>>(x, W, out);

    (void)n_in; (void)out_size;
}

// round 4
// speedup vs baseline: 1.3571x; 1.3571x over previous
#include <cuda_runtime.h>
#include <cuda_bf16.h>
#include <cstdint>

#define NV 50000
#define H 128

// Scratch (no cudaMalloc allowed)
__device__ float g_agg[(size_t)NV * H];   // 25.6 MB
__device__ float g_deg[NV];

// ---------------------------------------------------------------------------
// Zero scratch each launch
// ---------------------------------------------------------------------------
__global__ void k_zero() {
    size_t i = (size_t)blockIdx.x * blockDim.x + threadIdx.x;
    size_t stride = (size_t)gridDim.x * blockDim.x;
    float4 z = make_float4(0.f, 0.f, 0.f, 0.f);
    float4* a4 = reinterpret_cast<float4*>(g_agg);
    for (size_t t = i; t < (size_t)NV * H / 4; t += stride) a4[t] = z;
    for (size_t t = i; t < (size_t)NV; t += stride) g_deg[t] = 0.0f;
}

// ---------------------------------------------------------------------------
// Scatter: one warp per directed edge, red.global.add.v4.f32
// ---------------------------------------------------------------------------
__global__ void k_scatter(const float* __restrict__ x,
                          const int* __restrict__ ei, int nE) {
    int gw   = (int)(((unsigned)blockIdx.x * blockDim.x + threadIdx.x) >> 5);
    int lane = threadIdx.x & 31;
    if (gw >= 2 * nE) return;

    int s, d;
    if (gw < nE) { s = ei[gw];      d = ei[nE + gw]; }
    else         { int e = gw - nE; d = ei[e]; s = ei[nE + e]; }

    const float4* xs = reinterpret_cast<const float4*>(x + (size_t)s * H);
    float4 v = xs[lane];

    float4* ag = reinterpret_cast<float4*>(g_agg + (size_t)d * H) + lane;
    asm volatile("red.global.add.v4.f32 [%0], {%1, %2, %3, %4};"
                 :: "l"(ag), "f"(v.x), "f"(v.y), "f"(v.z), "f"(v.w)
                 : "memory");

    if (lane == 0) atomicAdd(&g_deg[d], 1.0f);
}

// ---------------------------------------------------------------------------
// HMMA GEMM via warp-level mma.sync (arch-agnostic, works on compute_103):
//   out[M=NV, N=128] = A[M, K=256] @ W^T
//   A[:, 0:128) = agg,  A[:, 128:256) = deg(row) * x
// bf16 hi/lo split: acc += Ahi*Bhi + Ahi*Blo + Alo*Bhi (fp32 accum).
//
// CTA: 128x128 tile, 256 threads = 8 warps in 4(m) x 2(n) grid.
// Warp tile: 32(m) x 64(n) = 2 x 8 tiles of m16n8k16.
// Smem pitch = 40 bf16 (80 B) -> fragment LDS banks row*20+tig: conflict-free.
// ---------------------------------------------------------------------------
#define BK 32
#define PITCH 40

__device__ __forceinline__ uint32_t pack_bf2(float a, float b) {
    __nv_bfloat162 h = __floats2bfloat162_rn(a, b);   // low = a
    return *reinterpret_cast<uint32_t*>(&h);
}

__device__ __forceinline__ void mma_16816(float* c, const uint32_t* a,
                                          uint32_t b0, uint32_t b1) {
    asm volatile(
        "mma.sync.aligned.m16n8k16.row.col.f32.bf16.bf16.f32 "
        "{%0,%1,%2,%3}, {%4,%5,%6,%7}, {%8,%9}, {%0,%1,%2,%3};"
        : "+f"(c[0]), "+f"(c[1]), "+f"(c[2]), "+f"(c[3])
        : "r"(a[0]), "r"(a[1]), "r"(a[2]), "r"(a[3]), "r"(b0), "r"(b1));
}

__global__ __launch_bounds__(256)
void k_gemm(const float* __restrict__ x, const float* __restrict__ W,
            float* __restrict__ out) {
    __shared__ __align__(16) __nv_bfloat16 Ahi[128][PITCH];
    __shared__ __align__(16) __nv_bfloat16 Alo[128][PITCH];
    __shared__ __align__(16) __nv_bfloat16 Bhi[128][PITCH];
    __shared__ __align__(16) __nv_bfloat16 Blo[128][PITCH];

    const int tid    = threadIdx.x;
    const int wid    = tid >> 5;
    const int lane   = tid & 31;
    const int grp    = lane >> 2;      // 0..7
    const int tig    = lane & 3;       // 0..3
    const int warp_m = wid & 3;        // 4 warps along M
    const int warp_n = wid >> 2;       // 2 warps along N
    const int row0   = blockIdx.x * 128;

    float acc[2][8][4];
#pragma unroll
    for (int mi = 0; mi < 2; mi++)
#pragma unroll
        for (int ni = 0; ni < 8; ni++)
#pragma unroll
            for (int q = 0; q < 4; q++) acc[mi][ni][q] = 0.0f;

    for (int kt = 0; kt < 8; kt++) {          // K = 256 in chunks of 32
        __syncthreads();                       // previous compute done
        // ---- load A tile 128x32 f32 -> bf16 hi/lo (4 float4 per thread) ----
#pragma unroll
        for (int p = 0; p < 4; p++) {
            int idx  = p * 256 + tid;          // 0..1023
            int row  = idx >> 3;               // 0..127
            int colq = idx & 7;                // float4 group 0..7
            int grow = row0 + row;
            float4 v = make_float4(0.f, 0.f, 0.f, 0.f);
            if (grow < NV) {
                if (kt < 4) {
                    v = *reinterpret_cast<const float4*>(
                        g_agg + (size_t)grow * H + kt * BK + colq * 4);
                } else {
                    v = *reinterpret_cast<const float4*>(
                        x + (size_t)grow * H + (kt - 4) * BK + colq * 4);
                    float dg = g_deg[grow];
                    v.x *= dg; v.y *= dg; v.z *= dg; v.w *= dg;
                }
            }
            float hx = __bfloat162float(__float2bfloat16(v.x));
            float hy = __bfloat162float(__float2bfloat16(v.y));
            float hz = __bfloat162float(__float2bfloat16(v.z));
            float hw = __bfloat162float(__float2bfloat16(v.w));
            uint2 hp = make_uint2(pack_bf2(hx, hy), pack_bf2(hz, hw));
            uint2 lp = make_uint2(pack_bf2(v.x - hx, v.y - hy),
                                  pack_bf2(v.z - hz, v.w - hw));
            *reinterpret_cast<uint2*>(&Ahi[row][colq * 4]) = hp;
            *reinterpret_cast<uint2*>(&Alo[row][colq * 4]) = lp;
        }
        // ---- load B tile: Bs[n][k] = W[n][kt*32+k] (W row-major [128,256]) --
#pragma unroll
        for (int p = 0; p < 4; p++) {
            int idx  = p * 256 + tid;
            int n    = idx >> 3;
            int colq = idx & 7;
            float4 v = *reinterpret_cast<const float4*>(
                W + (size_t)n * (2 * H) + kt * BK + colq * 4);
            float hx = __bfloat162float(__float2bfloat16(v.x));
            float hy = __bfloat162float(__float2bfloat16(v.y));
            float hz = __bfloat162float(__float2bfloat16(v.z));
            float hw = __bfloat162float(__float2bfloat16(v.w));
            uint2 hp = make_uint2(pack_bf2(hx, hy), pack_bf2(hz, hw));
            uint2 lp = make_uint2(pack_bf2(v.x - hx, v.y - hy),
                                  pack_bf2(v.z - hz, v.w - hw));
            *reinterpret_cast<uint2*>(&Bhi[n][colq * 4]) = hp;
            *reinterpret_cast<uint2*>(&Blo[n][colq * 4]) = lp;
        }
        __syncthreads();

        // ---- compute: 2 k16-steps per BK chunk ----
#pragma unroll
        for (int ks = 0; ks < 2; ks++) {
            int kb = ks * 16 + tig * 2;        // bf16 column within chunk
            uint32_t ah[2][4], al[2][4];
#pragma unroll
            for (int mi = 0; mi < 2; mi++) {
                int r = warp_m * 32 + mi * 16 + grp;
                ah[mi][0] = *reinterpret_cast<const uint32_t*>(&Ahi[r][kb]);
                ah[mi][1] = *reinterpret_cast<const uint32_t*>(&Ahi[r + 8][kb]);
                ah[mi][2] = *reinterpret_cast<const uint32_t*>(&Ahi[r][kb + 8]);
                ah[mi][3] = *reinterpret_cast<const uint32_t*>(&Ahi[r + 8][kb + 8]);
                al[mi][0] = *reinterpret_cast<const uint32_t*>(&Alo[r][kb]);
                al[mi][1] = *reinterpret_cast<const uint32_t*>(&Alo[r + 8][kb]);
                al[mi][2] = *reinterpret_cast<const uint32_t*>(&Alo[r][kb + 8]);
                al[mi][3] = *reinterpret_cast<const uint32_t*>(&Alo[r + 8][kb + 8]);
            }
#pragma unroll
            for (int ni = 0; ni < 8; ni++) {
                int n = warp_n * 64 + ni * 8 + grp;
                uint32_t bh0 = *reinterpret_cast<const uint32_t*>(&Bhi[n][kb]);
                uint32_t bh1 = *reinterpret_cast<const uint32_t*>(&Bhi[n][kb + 8]);
                uint32_t bl0 = *reinterpret_cast<const uint32_t*>(&Blo[n][kb]);
                uint32_t bl1 = *reinterpret_cast<const uint32_t*>(&Blo[n][kb + 8]);
#pragma unroll
                for (int mi = 0; mi < 2; mi++) {
                    mma_16816(acc[mi][ni], ah[mi], bh0, bh1);
                    mma_16816(acc[mi][ni], ah[mi], bl0, bl1);
                    mma_16816(acc[mi][ni], al[mi], bh0, bh1);
                }
            }
        }
    }

    // ---- epilogue ----
#pragma unroll
    for (int mi = 0; mi < 2; mi++) {
        int r0 = row0 + warp_m * 32 + mi * 16 + grp;
#pragma unroll
        for (int ni = 0; ni < 8; ni++) {
            int col = warp_n * 64 + ni * 8 + tig * 2;
            if (r0 < NV)
                *reinterpret_cast<float2*>(out + (size_t)r0 * H + col) =
                    make_float2(acc[mi][ni][0], acc[mi][ni][1]);
            if (r0 + 8 < NV)
                *reinterpret_cast<float2*>(out + (size_t)(r0 + 8) * H + col) =
                    make_float2(acc[mi][ni][2], acc[mi][ni][3]);
        }
    }
}

// ---------------------------------------------------------------------------
extern "C" void kernel_launch(void* const* d_in, const int* in_sizes, int n_in,
                              void* d_out, int out_size) {
    const float* x  = (const float*)d_in[0];   // [NV, 128] f32
    const float* W  = (const float*)d_in[1];   // [128, 256] f32
    const int*   ei = (const int*)d_in[2];     // [2, E] i32
    float* out = (float*)d_out;                // [NV, 128] f32

    int nE = in_sizes[2] / 2;

    k_zero<<<2048, 256>>>();

    int nwarps  = 2 * nE;
    int nblocks = (nwarps * 32 + 255) / 256;
    k_scatter<<<nblocks, 256>>>(x, ei, nE);

    k_gemm<<<(NV + 127) / 128, 256>>>(x, W, out);

    (void)n_in; (void)out_size;
}